// round 6
// baseline (speedup 1.0000x reference)
#include <cuda_runtime.h>
#include <cuda_bf16.h>
#include <math.h>
#include <stdint.h>

#define BQ 8
#define CC 1024
#define DD 512
#define MROWS 32768            // B*N = 16*2048
#define EPSF 1e-6f

// ---- scratch (device globals; no allocation allowed) ----
__device__ float g_residual[(size_t)MROWS * DD];   // 64 MB fp32 residual
__device__ uint4 g_res_h4[(size_t)MROWS * 64];     // 32 MB bf16 hi  [row][512]
__device__ uint4 g_res_l4[(size_t)MROWS * 64];     // 32 MB bf16 lo
__device__ uint4 g_cb_h4[(size_t)BQ * CC * 64];    // 8 MB bf16 hi codebooks
__device__ uint4 g_cb_l4[(size_t)BQ * CC * 64];    // 8 MB bf16 lo
__device__ float g_cbsq[BQ * CC];
__device__ int   g_idx[MROWS];
__device__ float g_loss[BQ];

// ============================================================================
// portable PTX helpers (sm_80-level: cp.async, ldmatrix, mma.sync — no 'a' feats)
// ============================================================================
__device__ __forceinline__ uint32_t smem_to_u32(const void* p) {
    uint32_t a;
    asm("{ .reg .u64 t; cvta.to.shared.u64 t, %1; cvt.u32.u64 %0, t; }"
        : "=r"(a) : "l"(p));
    return a;
}
__device__ __forceinline__ void cpasync16(uint32_t dst, const void* src) {
    asm volatile("cp.async.cg.shared.global [%0], [%1], 16;" :: "r"(dst), "l"(src));
}
#define CP_COMMIT() asm volatile("cp.async.commit_group;" ::: "memory")
#define CP_WAIT(n)  asm volatile("cp.async.wait_group %0;" :: "n"(n) : "memory")

__device__ __forceinline__ void ldsm4(uint32_t& r0, uint32_t& r1, uint32_t& r2,
                                      uint32_t& r3, uint32_t addr) {
    asm volatile("ldmatrix.sync.aligned.m8n8.x4.shared.b16 {%0,%1,%2,%3}, [%4];"
                 : "=r"(r0), "=r"(r1), "=r"(r2), "=r"(r3) : "r"(addr));
}
__device__ __forceinline__ void mma16816(float* c, uint32_t a0, uint32_t a1,
                                         uint32_t a2, uint32_t a3,
                                         uint32_t b0, uint32_t b1) {
    asm volatile(
        "mma.sync.aligned.m16n8k16.row.col.f32.bf16.bf16.f32 "
        "{%0,%1,%2,%3}, {%4,%5,%6,%7}, {%8,%9}, {%0,%1,%2,%3};"
        : "+f"(c[0]), "+f"(c[1]), "+f"(c[2]), "+f"(c[3])
        : "r"(a0), "r"(a1), "r"(a2), "r"(a3), "r"(b0), "r"(b1));
}

// ---- bf16 split helper ----
__device__ __forceinline__ void split4(float4 v, ushort4& h, ushort4& l) {
    __nv_bfloat16 hx = __float2bfloat16_rn(v.x);
    __nv_bfloat16 hy = __float2bfloat16_rn(v.y);
    __nv_bfloat16 hz = __float2bfloat16_rn(v.z);
    __nv_bfloat16 hw = __float2bfloat16_rn(v.w);
    h.x = __bfloat16_as_ushort(hx); h.y = __bfloat16_as_ushort(hy);
    h.z = __bfloat16_as_ushort(hz); h.w = __bfloat16_as_ushort(hw);
    l.x = __bfloat16_as_ushort(__float2bfloat16_rn(v.x - __bfloat162float(hx)));
    l.y = __bfloat16_as_ushort(__float2bfloat16_rn(v.y - __bfloat162float(hy)));
    l.z = __bfloat16_as_ushort(__float2bfloat16_rn(v.z - __bfloat162float(hz)));
    l.w = __bfloat16_as_ushort(__float2bfloat16_rn(v.w - __bfloat162float(hw)));
}

// ---------------------------------------------------------------------------
// init: residual = x (fp32 + bf16 hi/lo), zero out_q section, zero losses
// ---------------------------------------------------------------------------
__global__ void init_kernel(const float* __restrict__ x, float* __restrict__ out_q) {
    size_t i  = (size_t)blockIdx.x * blockDim.x + threadIdx.x;
    size_t n4 = (size_t)MROWS * DD / 4;
    const float4* x4 = (const float4*)x;
    float4* r4 = (float4*)g_residual;
    float4* o4 = (float4*)out_q;
    ushort4* rh = (ushort4*)g_res_h4;
    ushort4* rl = (ushort4*)g_res_l4;
    float4 z = make_float4(0.f, 0.f, 0.f, 0.f);
    for (size_t k = i; k < n4; k += (size_t)gridDim.x * blockDim.x) {
        float4 v = x4[k];
        r4[k] = v;
        o4[k] = z;
        ushort4 h, l; split4(v, h, l);
        rh[k] = h; rl[k] = l;
    }
    if (i < BQ) g_loss[i] = 0.f;
}

// ---------------------------------------------------------------------------
// codebook: cb_sq + bf16 hi/lo conversion
// ---------------------------------------------------------------------------
__global__ void cbsq_kernel(const float* __restrict__ cb) {
    int row  = blockIdx.x * 8 + (threadIdx.x >> 5);   // 0 .. BQ*CC-1
    int lane = threadIdx.x & 31;
    const float4* p = (const float4*)(cb + (size_t)row * DD);
    ushort4* ch = (ushort4*)g_cb_h4;
    ushort4* cl = (ushort4*)g_cb_l4;
    float s = 0.f;
#pragma unroll
    for (int j = 0; j < 4; j++) {
        float4 v = p[lane + 32 * j];
        s += v.x * v.x + v.y * v.y + v.z * v.z + v.w * v.w;
        ushort4 h, l; split4(v, h, l);
        size_t q = (size_t)row * 128 + lane + 32 * j;
        ch[q] = h; cl[q] = l;
    }
#pragma unroll
    for (int o = 16; o; o >>= 1) s += __shfl_xor_sync(0xFFFFFFFFu, s, o);
    if (lane == 0) g_cbsq[row] = s;
}

// ---------------------------------------------------------------------------
// mma.sync distance GEMM + argmin.
// Logical K = 1536 bf16 (hh, lh, hl segments; ll dropped ~2^-34).
// CTA tile 256 rows x 128 codes (grid = 128 CTAs = one wave), warps 4M x 2N,
// warp tile 64x64 (cuts ldmatrix redundancy: A x2, B x4 over old layout).
// 4-stage cp.async pipeline, KC = 32 bf16 per chunk, smem pitch 80B.
// ---------------------------------------------------------------------------
#define CTAM    256
#define PITCH   80
#define ATILEB  (CTAM * PITCH)         // 20480
#define BTILEB  (128 * PITCH)          // 10240
#define STAGEB  (ATILEB + BTILEB)      // 30720
#define NSTAGE  4
#define NKC     48                     // 3 segments x 16 chunks
#define SMEM_DYN (NSTAGE * STAGEB)     // 122880

__device__ __forceinline__ void issue_chunk(
    uint32_t sb, int rowBase, int qi, int nt, int kc, int stage)
{
    int seg  = kc >> 4;                 // 0: hh, 1: lh, 2: hl
    int koff = (kc & 15) * 64;          // byte offset within 1024B row
    const char* Ab = (const char*)((seg == 1) ? g_res_l4 : g_res_h4);
    const char* Bb = (const char*)((seg == 2) ? g_cb_l4 : g_cb_h4);
    uint32_t base = sb + stage * STAGEB;
    int tid = threadIdx.x;
    size_t bRow = (size_t)(qi * CC + nt * 128);
#pragma unroll
    for (int i = 0; i < 4; i++) {       // A: 1024 granules (256 rows x 4)
        int g = tid + 256 * i;
        int r = g >> 2, c = g & 3;
        cpasync16(base + r * PITCH + c * 16,
                  Ab + (size_t)(rowBase + r) * 1024 + koff + c * 16);
    }
#pragma unroll
    for (int i = 0; i < 2; i++) {       // B: 512 granules (128 rows x 4)
        int g = tid + 256 * i;
        int r = g >> 2, c = g & 3;
        cpasync16(base + ATILEB + r * PITCH + c * 16,
                  Bb + (bRow + r) * 1024 + koff + c * 16);
    }
}

__global__ __launch_bounds__(256, 1) void dist_mma_kernel(int qi)
{
    extern __shared__ char smem[];
    __shared__ float redV[2][CTAM];
    __shared__ int   redI[2][CTAM];
    uint32_t sb = smem_to_u32(smem);

    const int tid  = threadIdx.x;
    const int wid  = tid >> 5;
    const int lane = tid & 31;
    const int rowBase = blockIdx.x * CTAM;
    const int wM = (wid & 3) * 64;      // warp row offset in tile (4 M-warps)
    const int wN = (wid >> 2) * 64;     // warp col offset in tile (2 N-warps)

    // ldmatrix per-lane offsets (within a stage buffer)
    const int aRow = lane & 15;
    const int aCol = (lane >> 4) * 16;
    const int bRowL = (lane & 7) + ((lane >> 4) << 3);
    const int bColL = ((lane >> 3) & 1) * 16;
    const uint32_t aOffBase = (uint32_t)((wM + aRow) * PITCH + aCol);
    const uint32_t bOffBase = (uint32_t)(ATILEB + (wN + bRowL) * PITCH + bColL);

    const float2* csq2 = (const float2*)(g_cbsq + qi * CC);

    // 8 argmin slots per thread: s = mf*2 + h, row = wM + mf*16 + h*8 + (lane>>2)
    float best[8];
    int   bestI[8];
#pragma unroll
    for (int s = 0; s < 8; s++) { best[s] = INFINITY; bestI[s] = 0x7fffffff; }

#pragma unroll 1
    for (int nt = 0; nt < 8; nt++) {
        float acc[4][8][4];
#pragma unroll
        for (int mf = 0; mf < 4; mf++)
#pragma unroll
            for (int nf = 0; nf < 8; nf++)
#pragma unroll
                for (int e = 0; e < 4; e++) acc[mf][nf][e] = 0.f;

        // pipeline prologue: stages 0,1,2
        issue_chunk(sb, rowBase, qi, nt, 0, 0); CP_COMMIT();
        issue_chunk(sb, rowBase, qi, nt, 1, 1); CP_COMMIT();
        issue_chunk(sb, rowBase, qi, nt, 2, 2); CP_COMMIT();

#pragma unroll 1
        for (int kc = 0; kc < NKC; kc++) {
            if (kc < NKC - 2) { CP_WAIT(2); } else if (kc == NKC - 2) { CP_WAIT(1); }
            else { CP_WAIT(0); }
            __syncthreads();
            if (kc + 3 < NKC) {
                issue_chunk(sb, rowBase, qi, nt, kc + 3, (kc + 3) & 3);
                CP_COMMIT();
            }

            uint32_t stageBase = sb + (kc & 3) * STAGEB;
#pragma unroll
            for (int k16 = 0; k16 < 2; k16++) {
                uint32_t a[4][4];
#pragma unroll
                for (int mf = 0; mf < 4; mf++)
                    ldsm4(a[mf][0], a[mf][1], a[mf][2], a[mf][3],
                          stageBase + aOffBase + mf * 16 * PITCH + k16 * 32);
#pragma unroll
                for (int np = 0; np < 4; np++) {
                    uint32_t b0, b1, b2, b3;
                    ldsm4(b0, b1, b2, b3,
                          stageBase + bOffBase + np * 16 * PITCH + k16 * 32);
#pragma unroll
                    for (int mf = 0; mf < 4; mf++) {
                        mma16816(acc[mf][np * 2],
                                 a[mf][0], a[mf][1], a[mf][2], a[mf][3], b0, b1);
                        mma16816(acc[mf][np * 2 + 1],
                                 a[mf][0], a[mf][1], a[mf][2], a[mf][3], b2, b3);
                    }
                }
            }
        }
        __syncthreads();   // drain before next nt reuses stage buffers

        // fold accumulators: v = csq[n] - 2*dot; first-min tie-break
#pragma unroll
        for (int mf = 0; mf < 4; mf++) {
#pragma unroll
            for (int nf = 0; nf < 8; nf++) {
                int n = nt * 128 + wN + nf * 8 + (lane & 3) * 2;
                float2 cq = csq2[n >> 1];
                float v0 = cq.x - 2.f * acc[mf][nf][0];
                float v1 = cq.y - 2.f * acc[mf][nf][1];
                float v2 = cq.x - 2.f * acc[mf][nf][2];
                float v3 = cq.y - 2.f * acc[mf][nf][3];
                int s0 = mf * 2, s1 = mf * 2 + 1;
                if (v0 < best[s0] || (v0 == best[s0] && n < bestI[s0]))
                    { best[s0] = v0; bestI[s0] = n; }
                if (v1 < best[s0] || (v1 == best[s0] && n + 1 < bestI[s0]))
                    { best[s0] = v1; bestI[s0] = n + 1; }
                if (v2 < best[s1] || (v2 == best[s1] && n < bestI[s1]))
                    { best[s1] = v2; bestI[s1] = n; }
                if (v3 < best[s1] || (v3 == best[s1] && n + 1 < bestI[s1]))
                    { best[s1] = v3; bestI[s1] = n + 1; }
            }
        }
    }

    // reduce across the 4 lanes sharing each row (lane & 3)
#pragma unroll
    for (int s = 0; s < 8; s++) {
#pragma unroll
        for (int o = 1; o <= 2; o <<= 1) {
            float ov = __shfl_xor_sync(0xFFFFFFFFu, best[s], o);
            int   oi = __shfl_xor_sync(0xFFFFFFFFu, bestI[s], o);
            if (ov < best[s] || (ov == best[s] && oi < bestI[s]))
                { best[s] = ov; bestI[s] = oi; }
        }
    }
    if ((lane & 3) == 0) {
        int wg = wid >> 2;
#pragma unroll
        for (int s = 0; s < 8; s++) {
            int rloc = wM + (s >> 1) * 16 + (s & 1) * 8 + (lane >> 2);
            redV[wg][rloc] = best[s];
            redI[wg][rloc] = bestI[s];
        }
    }
    __syncthreads();
    {
        float v0 = redV[0][tid]; int i0 = redI[0][tid];
        float v1 = redV[1][tid]; int i1 = redI[1][tid];
        if (v1 < v0 || (v1 == v0 && i1 < i0)) { v0 = v1; i0 = i1; }
        g_idx[rowBase + tid] = i0;
    }
}

// ---------------------------------------------------------------------------
// Rotation trick + residual/output update + loss + index write + bf16 split
// of the new residual (for the next stage's MMA). Warp per row.
// ---------------------------------------------------------------------------
__global__ void rotate_kernel(const float* __restrict__ cbs, int qi,
                              float* __restrict__ out_q,
                              float* __restrict__ out_if,
                              int writeIdx, int writeLoss, int writeConv)
{
    __shared__ float ws[8];
    int row  = blockIdx.x * 8 + (threadIdx.x >> 5);
    int lane = threadIdx.x & 31;
    float* zp = g_residual + (size_t)row * DD;
    int idx = g_idx[row];
    const float* qp = cbs + ((size_t)qi * CC + idx) * DD;

    float4 zv[4], qv[4];
    float zz = 0.f, qq = 0.f, zq = 0.f, ll = 0.f;
#pragma unroll
    for (int j = 0; j < 4; j++) {
        zv[j] = ((const float4*)zp)[lane + 32 * j];
        qv[j] = ((const float4*)qp)[lane + 32 * j];
        zz += zv[j].x*zv[j].x + zv[j].y*zv[j].y + zv[j].z*zv[j].z + zv[j].w*zv[j].w;
        qq += qv[j].x*qv[j].x + qv[j].y*qv[j].y + qv[j].z*qv[j].z + qv[j].w*qv[j].w;
        zq += zv[j].x*qv[j].x + zv[j].y*qv[j].y + zv[j].z*qv[j].z + zv[j].w*qv[j].w;
        float dx = qv[j].x - zv[j].x, dy = qv[j].y - zv[j].y;
        float dz = qv[j].z - zv[j].z, dw = qv[j].w - zv[j].w;
        ll += dx*dx + dy*dy + dz*dz + dw*dw;
    }
#pragma unroll
    for (int o = 16; o; o >>= 1) {
        zz += __shfl_xor_sync(0xFFFFFFFFu, zz, o);
        qq += __shfl_xor_sync(0xFFFFFFFFu, qq, o);
        zq += __shfl_xor_sync(0xFFFFFFFFu, zq, o);
        ll += __shfl_xor_sync(0xFFFFFFFFu, ll, o);
    }

    float nz = sqrtf(zz), nq = sqrtf(qq);
    float iz = 1.f / (nz + EPSF), iq = 1.f / (nq + EPSF);
    float s2 = zz * iz * iz + 2.f * zq * iz * iq + qq * iq * iq;
    float A2 = 2.f * (zz * iz + zq * iq) / s2;
    float Bc = 2.f * zz * iz * iq;
    float cz = 1.f - A2 * iz;
    float cq = Bc - A2 * iq;
    float sc = nq * iz;

    float* op = out_q + (size_t)row * DD;
    ushort4* rh = (ushort4*)g_res_h4;
    ushort4* rl = (ushort4*)g_res_l4;
#pragma unroll
    for (int j = 0; j < 4; j++) {
        float4 z = zv[j], q = qv[j], t, r, o;
        t.x = (z.x * cz + q.x * cq) * sc;
        t.y = (z.y * cz + q.y * cq) * sc;
        t.z = (z.z * cz + q.z * cq) * sc;
        t.w = (z.w * cz + q.w * cq) * sc;
        r.x = z.x - t.x; r.y = z.y - t.y; r.z = z.z - t.z; r.w = z.w - t.w;
        ((float4*)zp)[lane + 32 * j] = r;
        o = ((float4*)op)[lane + 32 * j];
        o.x += t.x; o.y += t.y; o.z += t.z; o.w += t.w;
        ((float4*)op)[lane + 32 * j] = o;
        if (writeConv) {
            ushort4 h, l; split4(r, h, l);
            size_t e = (size_t)row * 128 + lane + 32 * j;
            rh[e] = h; rl[e] = l;
        }
    }

    if (writeIdx && lane == 0)
        out_if[(size_t)row * BQ + qi] = (float)idx;

    if (writeLoss) {
        if (lane == 0) ws[threadIdx.x >> 5] = ll;
        __syncthreads();
        if (threadIdx.x == 0) {
            float s = 0.f;
#pragma unroll
            for (int w = 0; w < 8; w++) s += ws[w];
            atomicAdd(&g_loss[qi], s);
        }
    }
}

// ---------------------------------------------------------------------------
__global__ void final_kernel(float* __restrict__ out_loss) {
    int i = threadIdx.x;
    if (i < BQ) out_loss[i] = g_loss[i] / (float)((size_t)MROWS * DD);
}

// ---------------------------------------------------------------------------
extern "C" void kernel_launch(void* const* d_in, const int* in_sizes, int n_in,
                              void* d_out, int out_size) {
    const float* x   = (const float*)d_in[0];
    const float* cbs = (const float*)d_in[1];
    if (n_in >= 2 && in_sizes[0] == BQ * CC * DD && in_sizes[1] == MROWS * DD) {
        const float* t = x; x = cbs; cbs = t;
    }

    float* out = (float*)d_out;
    const long long qElems = (long long)MROWS * DD;   // 16777216
    const long long iElems = (long long)MROWS * BQ;   // 262144
    float* out_q = out;
    float* out_i = out + qElems;
    float* out_l = out + qElems + iElems;
    int haveIdx  = (out_size >= qElems + iElems) ? 1 : 0;
    int haveLoss = (out_size >= qElems + iElems + BQ) ? 1 : 0;

    static int attrSet = 0;
    if (!attrSet) {
        cudaFuncSetAttribute(dist_mma_kernel,
                             cudaFuncAttributeMaxDynamicSharedMemorySize, SMEM_DYN);
        attrSet = 1;
    }

    init_kernel<<<1024, 256>>>(x, out_q);
    cbsq_kernel<<<BQ * CC / 8, 256>>>(cbs);

    for (int qi = 0; qi < BQ; qi++) {
        dist_mma_kernel<<<MROWS / CTAM, 256, SMEM_DYN>>>(qi);
        rotate_kernel<<<MROWS / 8, 256>>>(cbs, qi, out_q, out_i,
                                          haveIdx, haveLoss, qi < BQ - 1);
    }

    if (haveLoss) final_kernel<<<1, 32>>>(out_l);
}

// round 7
// speedup vs baseline: 1.0114x; 1.0114x over previous
#include <cuda_runtime.h>
#include <cuda_bf16.h>
#include <math.h>
#include <stdint.h>

#define BQ 8
#define CC 1024
#define DD 512
#define MROWS 32768            // B*N = 16*2048
#define EPSF 1e-6f

// ---- scratch (device globals; no allocation allowed) ----
__device__ float g_residual[(size_t)MROWS * DD];   // 64 MB fp32 residual
__device__ uint4 g_res_h4[(size_t)MROWS * 64];     // 32 MB bf16 hi  [row][512]
__device__ uint4 g_cb_h4[(size_t)BQ * CC * 64];    // 8 MB bf16 hi codebooks
__device__ float g_cbsq[BQ * CC];
__device__ int   g_cmaxi[BQ];                      // max csq per codebook (as int bits)
__device__ uint4 g_cand[(size_t)MROWS * 16];       // per row: 8 contribs x 2 uint4
__device__ float g_loss[BQ];

// ============================================================================
// portable PTX helpers (sm_80-level: cp.async, ldmatrix, mma.sync)
// ============================================================================
__device__ __forceinline__ uint32_t smem_to_u32(const void* p) {
    uint32_t a;
    asm("{ .reg .u64 t; cvta.to.shared.u64 t, %1; cvt.u32.u64 %0, t; }"
        : "=r"(a) : "l"(p));
    return a;
}
__device__ __forceinline__ void cpasync16(uint32_t dst, const void* src) {
    asm volatile("cp.async.cg.shared.global [%0], [%1], 16;" :: "r"(dst), "l"(src));
}
#define CP_COMMIT() asm volatile("cp.async.commit_group;" ::: "memory")
#define CP_WAIT(n)  asm volatile("cp.async.wait_group %0;" :: "n"(n) : "memory")

__device__ __forceinline__ void ldsm4(uint32_t& r0, uint32_t& r1, uint32_t& r2,
                                      uint32_t& r3, uint32_t addr) {
    asm volatile("ldmatrix.sync.aligned.m8n8.x4.shared.b16 {%0,%1,%2,%3}, [%4];"
                 : "=r"(r0), "=r"(r1), "=r"(r2), "=r"(r3) : "r"(addr));
}
__device__ __forceinline__ void mma16816(float* c, uint32_t a0, uint32_t a1,
                                         uint32_t a2, uint32_t a3,
                                         uint32_t b0, uint32_t b1) {
    asm volatile(
        "mma.sync.aligned.m16n8k16.row.col.f32.bf16.bf16.f32 "
        "{%0,%1,%2,%3}, {%4,%5,%6,%7}, {%8,%9}, {%0,%1,%2,%3};"
        : "+f"(c[0]), "+f"(c[1]), "+f"(c[2]), "+f"(c[3])
        : "r"(a0), "r"(a1), "r"(a2), "r"(a3), "r"(b0), "r"(b1));
}

__device__ __forceinline__ ushort4 hi4(float4 v) {
    ushort4 h;
    h.x = __bfloat16_as_ushort(__float2bfloat16_rn(v.x));
    h.y = __bfloat16_as_ushort(__float2bfloat16_rn(v.y));
    h.z = __bfloat16_as_ushort(__float2bfloat16_rn(v.z));
    h.w = __bfloat16_as_ushort(__float2bfloat16_rn(v.w));
    return h;
}

// top-3 + 4th-value insert (strict <; dropped ties at v4 are covered by the
// overflow flag since then v4 itself is inside the window)
__device__ __forceinline__ void ins4(float& v1, int& i1, float& v2, int& i2,
                                     float& v3, int& i3, float& v4,
                                     float v, int n) {
    if (v < v4) {
        if (v < v1)      { v4 = v3; v3 = v2; i3 = i2; v2 = v1; i2 = i1; v1 = v; i1 = n; }
        else if (v < v2) { v4 = v3; v3 = v2; i3 = i2; v2 = v; i2 = n; }
        else if (v < v3) { v4 = v3; v3 = v; i3 = n; }
        else             { v4 = v; }
    }
}

// ---------------------------------------------------------------------------
// init: residual = x (fp32 + bf16 hi), reset loss/cmax. Warp per row.
// ---------------------------------------------------------------------------
__global__ void init_kernel(const float* __restrict__ x) {
    int row  = blockIdx.x * 8 + (threadIdx.x >> 5);
    int lane = threadIdx.x & 31;
    const float4* xp = (const float4*)(x + (size_t)row * DD);
    float4* rp = (float4*)(g_residual + (size_t)row * DD);
    ushort4* rh = (ushort4*)g_res_h4;
#pragma unroll
    for (int j = 0; j < 4; j++) {
        float4 v = xp[lane + 32 * j];
        rp[lane + 32 * j] = v;
        rh[(size_t)row * 128 + lane + 32 * j] = hi4(v);
    }
    if (blockIdx.x == 0 && threadIdx.x < BQ) {
        g_loss[threadIdx.x] = 0.f;
        g_cmaxi[threadIdx.x] = 0;
    }
}

// ---------------------------------------------------------------------------
// codebook: cb_sq + bf16 hi conversion + per-codebook max csq
// ---------------------------------------------------------------------------
__global__ void cbsq_kernel(const float* __restrict__ cb) {
    int row  = blockIdx.x * 8 + (threadIdx.x >> 5);   // 0 .. BQ*CC-1
    int lane = threadIdx.x & 31;
    const float4* p = (const float4*)(cb + (size_t)row * DD);
    ushort4* ch = (ushort4*)g_cb_h4;
    float s = 0.f;
#pragma unroll
    for (int j = 0; j < 4; j++) {
        float4 v = p[lane + 32 * j];
        s += v.x * v.x + v.y * v.y + v.z * v.z + v.w * v.w;
        ch[(size_t)row * 128 + lane + 32 * j] = hi4(v);
    }
#pragma unroll
    for (int o = 16; o; o >>= 1) s += __shfl_xor_sync(0xFFFFFFFFu, s, o);
    if (lane == 0) {
        g_cbsq[row] = s;
        atomicMax(&g_cmaxi[row >> 10], __float_as_int(s));
    }
}

// ---------------------------------------------------------------------------
// hh-only distance GEMM (K=512 bf16) with per-thread top-3+v4 candidate lists.
// CTA tile 128 rows x 128 codes, 8 N-tiles (all 1024 codes). 4-stage cp.async.
// Exact argmin is recovered later by windowed exact rescore in rotate_kernel.
// ---------------------------------------------------------------------------
#define PITCH   80
#define TILEB   (128 * PITCH)          // 10240 per operand
#define STAGEB  (2 * TILEB)            // 20480 A+B
#define NKC     16                     // hh segment only: 16 x 32 bf16 = 512
#define SMEM_DYN (4 * STAGEB)          // 81920

__device__ __forceinline__ void issue_chunk(
    uint32_t sb, int rowBase, int qi, int nt, int kc, int stage)
{
    int koff = kc * 64;                 // byte offset within 1024B hi row
    uint32_t base = sb + stage * STAGEB;
    int tid = threadIdx.x;
    size_t bRow = (size_t)(qi * CC + nt * 128);
#pragma unroll
    for (int i = 0; i < 2; i++) {
        int g = tid + 256 * i;          // 0..511
        int r = g >> 2, c = g & 3;
        cpasync16(base + r * PITCH + c * 16,
                  (const char*)g_res_h4 + (size_t)(rowBase + r) * 1024 + koff + c * 16);
        cpasync16(base + TILEB + r * PITCH + c * 16,
                  (const char*)g_cb_h4 + (bRow + r) * 1024 + koff + c * 16);
    }
}

__global__ __launch_bounds__(256, 2) void dist_mma_kernel(int qi)
{
    extern __shared__ char smem[];
    uint32_t sb = smem_to_u32(smem);

    const int tid  = threadIdx.x;
    const int wid  = tid >> 5;
    const int lane = tid & 31;
    const int rowBase = blockIdx.x * 128;
    const int wM = (wid & 3) * 32;      // warp row offset
    const int wN = (wid >> 2) * 64;     // warp col offset

    const int aRow = lane & 15;
    const int aCol = (lane >> 4) * 16;
    const int bRowL = (lane & 7) + ((lane >> 4) << 3);
    const int bColL = ((lane >> 3) & 1) * 16;
    const uint32_t aOffBase = (uint32_t)((wM + aRow) * PITCH + aCol);
    const uint32_t bOffBase = (uint32_t)(TILEB + (wN + bRowL) * PITCH + bColL);

    const float2* csq2 = (const float2*)(g_cbsq + qi * CC);

    float cv1[4], cv2[4], cv3[4], cv4[4];
    int   ci1[4], ci2[4], ci3[4];
#pragma unroll
    for (int s = 0; s < 4; s++) {
        cv1[s] = INFINITY; cv2[s] = INFINITY; cv3[s] = INFINITY; cv4[s] = INFINITY;
        ci1[s] = 0x7fffffff; ci2[s] = 0x7fffffff; ci3[s] = 0x7fffffff;
    }

#pragma unroll 1
    for (int nt = 0; nt < 8; nt++) {
        float acc[2][8][4];
#pragma unroll
        for (int mf = 0; mf < 2; mf++)
#pragma unroll
            for (int nf = 0; nf < 8; nf++)
#pragma unroll
                for (int e = 0; e < 4; e++) acc[mf][nf][e] = 0.f;

        issue_chunk(sb, rowBase, qi, nt, 0, 0); CP_COMMIT();
        issue_chunk(sb, rowBase, qi, nt, 1, 1); CP_COMMIT();
        issue_chunk(sb, rowBase, qi, nt, 2, 2); CP_COMMIT();

#pragma unroll 1
        for (int kc = 0; kc < NKC; kc++) {
            if (kc < NKC - 2) { CP_WAIT(2); } else if (kc == NKC - 2) { CP_WAIT(1); }
            else { CP_WAIT(0); }
            __syncthreads();
            if (kc + 3 < NKC) {
                issue_chunk(sb, rowBase, qi, nt, kc + 3, (kc + 3) & 3);
                CP_COMMIT();
            }

            uint32_t stageBase = sb + (kc & 3) * STAGEB;
#pragma unroll
            for (int k16 = 0; k16 < 2; k16++) {
                uint32_t a[2][4];
#pragma unroll
                for (int mf = 0; mf < 2; mf++)
                    ldsm4(a[mf][0], a[mf][1], a[mf][2], a[mf][3],
                          stageBase + aOffBase + mf * 16 * PITCH + k16 * 32);
#pragma unroll
                for (int np = 0; np < 4; np++) {
                    uint32_t b0, b1, b2, b3;
                    ldsm4(b0, b1, b2, b3,
                          stageBase + bOffBase + np * 16 * PITCH + k16 * 32);
#pragma unroll
                    for (int mf = 0; mf < 2; mf++) {
                        mma16816(acc[mf][np * 2],
                                 a[mf][0], a[mf][1], a[mf][2], a[mf][3], b0, b1);
                        mma16816(acc[mf][np * 2 + 1],
                                 a[mf][0], a[mf][1], a[mf][2], a[mf][3], b2, b3);
                    }
                }
            }
        }
        __syncthreads();   // drain before next nt reuses stage buffers

        // fold into candidate lists: v = csq[n] - 2*acc
#pragma unroll
        for (int mf = 0; mf < 2; mf++) {
#pragma unroll
            for (int nf = 0; nf < 8; nf++) {
                int n = nt * 128 + wN + nf * 8 + (lane & 3) * 2;
                float2 cq = csq2[n >> 1];
                float v0 = cq.x - 2.f * acc[mf][nf][0];
                float v1 = cq.y - 2.f * acc[mf][nf][1];
                float v2 = cq.x - 2.f * acc[mf][nf][2];
                float v3 = cq.y - 2.f * acc[mf][nf][3];
                int s0 = mf * 2, s1 = mf * 2 + 1;
                ins4(cv1[s0], ci1[s0], cv2[s0], ci2[s0], cv3[s0], ci3[s0], cv4[s0], v0, n);
                ins4(cv1[s0], ci1[s0], cv2[s0], ci2[s0], cv3[s0], ci3[s0], cv4[s0], v1, n + 1);
                ins4(cv1[s1], ci1[s1], cv2[s1], ci2[s1], cv3[s1], ci3[s1], cv4[s1], v2, n);
                ins4(cv1[s1], ci1[s1], cv2[s1], ci2[s1], cv3[s1], ci3[s1], cv4[s1], v3, n + 1);
            }
        }
    }

    // epilogue: dump candidate lists, one contrib slot per (thread, s)
#pragma unroll
    for (int s = 0; s < 4; s++) {
        int row = rowBase + wM + (s >> 1) * 16 + (s & 1) * 8 + (lane >> 2);
        int contrib = (wid >> 2) * 4 + (lane & 3);
        size_t base = ((size_t)row * 8 + contrib) * 2;
        g_cand[base] = make_uint4(__float_as_uint(cv1[s]), (uint32_t)ci1[s],
                                  __float_as_uint(cv2[s]), (uint32_t)ci2[s]);
        g_cand[base + 1] = make_uint4(__float_as_uint(cv3[s]), (uint32_t)ci3[s],
                                      __float_as_uint(cv4[s]), 0u);
    }
}

// ---------------------------------------------------------------------------
// Exact argmin selection (windowed rescore / rare full scan) + rotation trick
// + residual update + loss + index write + bf16 hi of new residual.
// Warp per row.
// ---------------------------------------------------------------------------
__global__ void rotate_kernel(const float* __restrict__ cbs, int qi,
                              float* __restrict__ out_if,
                              int writeIdx, int writeLoss, int writeConv)
{
    __shared__ float ws[8];
    __shared__ int candList[8][24];
    int wslot = threadIdx.x >> 5;
    int row  = blockIdx.x * 8 + wslot;
    int lane = threadIdx.x & 31;
    float* zp = g_residual + (size_t)row * DD;

    float4 zv[4];
    float zz = 0.f;
#pragma unroll
    for (int j = 0; j < 4; j++) {
        zv[j] = ((const float4*)zp)[lane + 32 * j];
        zz += zv[j].x*zv[j].x + zv[j].y*zv[j].y + zv[j].z*zv[j].z + zv[j].w*zv[j].w;
    }
#pragma unroll
    for (int o = 16; o; o >>= 1) zz += __shfl_xor_sync(0xFFFFFFFFu, zz, o);
    float nz = sqrtf(zz);

    // ---- exact argmin selection ----
    float v1 = INFINITY, v2 = INFINITY, v3 = INFINITY, v4 = INFINITY;
    int i1 = 0x7fffffff, i2 = 0x7fffffff, i3 = 0x7fffffff;
    if (lane < 8) {
        uint4 a = g_cand[((size_t)row * 8 + lane) * 2];
        uint4 b = g_cand[((size_t)row * 8 + lane) * 2 + 1];
        v1 = __uint_as_float(a.x); i1 = (int)a.y;
        v2 = __uint_as_float(a.z); i2 = (int)a.w;
        v3 = __uint_as_float(b.x); i3 = (int)b.y;
        v4 = __uint_as_float(b.z);
    }
    float m = v1;
#pragma unroll
    for (int o = 16; o; o >>= 1) m = fminf(m, __shfl_xor_sync(0xFFFFFFFFu, m, o));
    float cmax_s = sqrtf(__int_as_float(g_cmaxi[qi]));
    // |dtilde - d| <= 2 * 2^-8 * (|r||c| + |rh||c|) + fp32-accum slack
    float win = m + 0.017f * nz * cmax_s + 0.2f;
    const float* csq = g_cbsq + qi * CC;

    bool ofl = __ballot_sync(0xFFFFFFFFu, v4 <= win) != 0;
    int myc = (v1 <= win ? 1 : 0) + (v2 <= win ? 1 : 0) + (v3 <= win ? 1 : 0);
    int tot = myc;
#pragma unroll
    for (int o = 16; o; o >>= 1) tot += __shfl_xor_sync(0xFFFFFFFFu, tot, o);

    int idx;
    if (!ofl && tot == 1) {
        unsigned bb = __ballot_sync(0xFFFFFFFFu, v1 == m);
        idx = __shfl_sync(0xFFFFFFFFu, i1, __ffs(bb) - 1);
    } else if (!ofl) {
        int off = myc;
#pragma unroll
        for (int o = 1; o < 32; o <<= 1) {
            int t = __shfl_up_sync(0xFFFFFFFFu, off, o);
            if (lane >= o) off += t;
        }
        off -= myc;
        if (lane < 8) {
            int p = off;
            if (v1 <= win) candList[wslot][p++] = i1;
            if (v2 <= win) candList[wslot][p++] = i2;
            if (v3 <= win) candList[wslot][p++] = i3;
        }
        __syncwarp();
        float bd = INFINITY; int bi = 0x7fffffff;
        for (int j = 0; j < tot; j++) {
            int c = candList[wslot][j];
            const float4* qp4 = (const float4*)(cbs + ((size_t)qi * CC + c) * DD);
            float s = 0.f;
#pragma unroll
            for (int jj = 0; jj < 4; jj++) {
                float4 q = qp4[lane + 32 * jj];
                s += zv[jj].x*q.x + zv[jj].y*q.y + zv[jj].z*q.z + zv[jj].w*q.w;
            }
#pragma unroll
            for (int o = 16; o; o >>= 1) s += __shfl_xor_sync(0xFFFFFFFFu, s, o);
            float d = csq[c] - 2.f * s;
            if (d < bd || (d == bd && c < bi)) { bd = d; bi = c; }
        }
        idx = bi;
    } else {
        // rare: possible dropped candidate -> exact full scan
        float bd = INFINITY; int bi = 0x7fffffff;
        for (int c = 0; c < CC; c++) {
            const float4* qp4 = (const float4*)(cbs + ((size_t)qi * CC + c) * DD);
            float s = 0.f;
#pragma unroll
            for (int jj = 0; jj < 4; jj++) {
                float4 q = qp4[lane + 32 * jj];
                s += zv[jj].x*q.x + zv[jj].y*q.y + zv[jj].z*q.z + zv[jj].w*q.w;
            }
#pragma unroll
            for (int o = 16; o; o >>= 1) s += __shfl_xor_sync(0xFFFFFFFFu, s, o);
            float d = csq[c] - 2.f * s;
            if (d < bd || (d == bd && c < bi)) { bd = d; bi = c; }
        }
        idx = bi;
    }

    // ---- rotation trick ----
    const float* qp = cbs + ((size_t)qi * CC + idx) * DD;
    float4 qv[4];
    float qq = 0.f, zq = 0.f, ll = 0.f;
#pragma unroll
    for (int j = 0; j < 4; j++) {
        qv[j] = ((const float4*)qp)[lane + 32 * j];
        qq += qv[j].x*qv[j].x + qv[j].y*qv[j].y + qv[j].z*qv[j].z + qv[j].w*qv[j].w;
        zq += zv[j].x*qv[j].x + zv[j].y*qv[j].y + zv[j].z*qv[j].z + zv[j].w*qv[j].w;
        float dx = qv[j].x - zv[j].x, dy = qv[j].y - zv[j].y;
        float dz = qv[j].z - zv[j].z, dw = qv[j].w - zv[j].w;
        ll += dx*dx + dy*dy + dz*dz + dw*dw;
    }
#pragma unroll
    for (int o = 16; o; o >>= 1) {
        qq += __shfl_xor_sync(0xFFFFFFFFu, qq, o);
        zq += __shfl_xor_sync(0xFFFFFFFFu, zq, o);
        ll += __shfl_xor_sync(0xFFFFFFFFu, ll, o);
    }

    float nq = sqrtf(qq);
    float iz = 1.f / (nz + EPSF), iq = 1.f / (nq + EPSF);
    float s2 = zz * iz * iz + 2.f * zq * iz * iq + qq * iq * iq;
    float A2 = 2.f * (zz * iz + zq * iq) / s2;
    float Bc = 2.f * zz * iz * iq;
    float cz = 1.f - A2 * iz;
    float cq = Bc - A2 * iq;
    float sc = nq * iz;

    ushort4* rh = (ushort4*)g_res_h4;
#pragma unroll
    for (int j = 0; j < 4; j++) {
        float4 z = zv[j], q = qv[j], t, r;
        t.x = (z.x * cz + q.x * cq) * sc;
        t.y = (z.y * cz + q.y * cq) * sc;
        t.z = (z.z * cz + q.z * cq) * sc;
        t.w = (z.w * cz + q.w * cq) * sc;
        r.x = z.x - t.x; r.y = z.y - t.y; r.z = z.z - t.z; r.w = z.w - t.w;
        ((float4*)zp)[lane + 32 * j] = r;
        if (writeConv)
            rh[(size_t)row * 128 + lane + 32 * j] = hi4(r);
    }

    if (writeIdx && lane == 0)
        out_if[(size_t)row * BQ + qi] = (float)idx;

    if (writeLoss) {
        if (lane == 0) ws[wslot] = ll;
        __syncthreads();
        if (threadIdx.x == 0) {
            float s = 0.f;
#pragma unroll
            for (int w = 0; w < 8; w++) s += ws[w];
            atomicAdd(&g_loss[qi], s);
        }
    }
}

// ---------------------------------------------------------------------------
// out_q = x - residual_final  (sum of quants telescopes)
// ---------------------------------------------------------------------------
__global__ void outq_kernel(const float* __restrict__ x, float* __restrict__ out_q) {
    size_t i  = (size_t)blockIdx.x * blockDim.x + threadIdx.x;
    size_t n4 = (size_t)MROWS * DD / 4;
    const float4* x4 = (const float4*)x;
    const float4* r4 = (const float4*)g_residual;
    float4* o4 = (float4*)out_q;
    for (size_t k = i; k < n4; k += (size_t)gridDim.x * blockDim.x) {
        float4 a = x4[k], b = r4[k];
        o4[k] = make_float4(a.x - b.x, a.y - b.y, a.z - b.z, a.w - b.w);
    }
}

// ---------------------------------------------------------------------------
__global__ void final_kernel(float* __restrict__ out_loss) {
    int i = threadIdx.x;
    if (i < BQ) out_loss[i] = g_loss[i] / (float)((size_t)MROWS * DD);
}

// ---------------------------------------------------------------------------
extern "C" void kernel_launch(void* const* d_in, const int* in_sizes, int n_in,
                              void* d_out, int out_size) {
    const float* x   = (const float*)d_in[0];
    const float* cbs = (const float*)d_in[1];
    if (n_in >= 2 && in_sizes[0] == BQ * CC * DD && in_sizes[1] == MROWS * DD) {
        const float* t = x; x = cbs; cbs = t;
    }

    float* out = (float*)d_out;
    const long long qElems = (long long)MROWS * DD;   // 16777216
    const long long iElems = (long long)MROWS * BQ;   // 262144
    float* out_q = out;
    float* out_i = out + qElems;
    float* out_l = out + qElems + iElems;
    int haveIdx  = (out_size >= qElems + iElems) ? 1 : 0;
    int haveLoss = (out_size >= qElems + iElems + BQ) ? 1 : 0;

    static int attrSet = 0;
    if (!attrSet) {
        cudaFuncSetAttribute(dist_mma_kernel,
                             cudaFuncAttributeMaxDynamicSharedMemorySize, SMEM_DYN);
        attrSet = 1;
    }

    init_kernel<<<MROWS / 8, 256>>>(x);
    cbsq_kernel<<<BQ * CC / 8, 256>>>(cbs);

    for (int qi = 0; qi < BQ; qi++) {
        dist_mma_kernel<<<MROWS / 128, 256, SMEM_DYN>>>(qi);
        rotate_kernel<<<MROWS / 8, 256>>>(cbs, qi, out_i,
                                          haveIdx, haveLoss, qi < BQ - 1);
    }

    outq_kernel<<<1024, 256>>>(x, out_q);
    if (haveLoss) final_kernel<<<1, 32>>>(out_l);
}

// round 8
// speedup vs baseline: 1.7616x; 1.7416x over previous
#include <cuda_runtime.h>
#include <cuda_bf16.h>
#include <math.h>
#include <stdint.h>

#define BQ 8
#define CC 1024
#define DD 512
#define MROWS 32768            // B*N = 16*2048
#define EPSF 1e-6f

// ---- scratch (device globals; no allocation allowed) ----
__device__ float g_residual[(size_t)MROWS * DD];   // 64 MB fp32 residual
__device__ uint4 g_res_h4[(size_t)MROWS * 64];     // 32 MB bf16 hi  [row][512]
__device__ uint4 g_cb_h4[(size_t)BQ * CC * 64];    // 8 MB bf16 hi codebooks
__device__ float g_cbsq[BQ * CC];
__device__ float g_nl[MROWS];                      // per-row lo-norm ||r - bf16(r)||
__device__ int   g_cmaxi[BQ];                      // max csq per codebook (bits)
__device__ int   g_nlcmaxi[BQ];                    // max lo-norm^2 per codebook (bits)
__device__ uint4 g_cand[(size_t)MROWS * 16];       // per row: 8 contribs x 2 uint4
__device__ float g_loss[BQ];

// ============================================================================
// portable PTX helpers (sm_80-level: cp.async, ldmatrix, mma.sync)
// ============================================================================
__device__ __forceinline__ uint32_t smem_to_u32(const void* p) {
    uint32_t a;
    asm("{ .reg .u64 t; cvta.to.shared.u64 t, %1; cvt.u32.u64 %0, t; }"
        : "=r"(a) : "l"(p));
    return a;
}
__device__ __forceinline__ void cpasync16(uint32_t dst, const void* src) {
    asm volatile("cp.async.cg.shared.global [%0], [%1], 16;" :: "r"(dst), "l"(src));
}
#define CP_COMMIT() asm volatile("cp.async.commit_group;" ::: "memory")
#define CP_WAIT(n)  asm volatile("cp.async.wait_group %0;" :: "n"(n) : "memory")

__device__ __forceinline__ void ldsm4(uint32_t& r0, uint32_t& r1, uint32_t& r2,
                                      uint32_t& r3, uint32_t addr) {
    asm volatile("ldmatrix.sync.aligned.m8n8.x4.shared.b16 {%0,%1,%2,%3}, [%4];"
                 : "=r"(r0), "=r"(r1), "=r"(r2), "=r"(r3) : "r"(addr));
}
__device__ __forceinline__ void mma16816(float* c, uint32_t a0, uint32_t a1,
                                         uint32_t a2, uint32_t a3,
                                         uint32_t b0, uint32_t b1) {
    asm volatile(
        "mma.sync.aligned.m16n8k16.row.col.f32.bf16.bf16.f32 "
        "{%0,%1,%2,%3}, {%4,%5,%6,%7}, {%8,%9}, {%0,%1,%2,%3};"
        : "+f"(c[0]), "+f"(c[1]), "+f"(c[2]), "+f"(c[3])
        : "r"(a0), "r"(a1), "r"(a2), "r"(a3), "r"(b0), "r"(b1));
}

__device__ __forceinline__ ushort4 hi4(float4 v) {
    ushort4 h;
    h.x = __bfloat16_as_ushort(__float2bfloat16_rn(v.x));
    h.y = __bfloat16_as_ushort(__float2bfloat16_rn(v.y));
    h.z = __bfloat16_as_ushort(__float2bfloat16_rn(v.z));
    h.w = __bfloat16_as_ushort(__float2bfloat16_rn(v.w));
    return h;
}
__device__ __forceinline__ float losq4(float4 v, ushort4 h) {
    float dx = v.x - __bfloat162float(__ushort_as_bfloat16(h.x));
    float dy = v.y - __bfloat162float(__ushort_as_bfloat16(h.y));
    float dz = v.z - __bfloat162float(__ushort_as_bfloat16(h.z));
    float dw = v.w - __bfloat162float(__ushort_as_bfloat16(h.w));
    return dx*dx + dy*dy + dz*dz + dw*dw;
}

// top-3 + 4th-value insert
__device__ __forceinline__ void ins4(float& v1, int& i1, float& v2, int& i2,
                                     float& v3, int& i3, float& v4,
                                     float v, int n) {
    if (v < v4) {
        if (v < v1)      { v4 = v3; v3 = v2; i3 = i2; v2 = v1; i2 = i1; v1 = v; i1 = n; }
        else if (v < v2) { v4 = v3; v3 = v2; i3 = i2; v2 = v; i2 = n; }
        else if (v < v3) { v4 = v3; v3 = v; i3 = n; }
        else             { v4 = v; }
    }
}

// warp-cooperative exact distance of row (zv in regs) vs code c
__device__ __forceinline__ float exact_d(const float* __restrict__ cbs,
                                         const float* __restrict__ csq,
                                         int qi, int c, const float4* zv, int lane) {
    const float4* qp4 = (const float4*)(cbs + ((size_t)qi * CC + c) * DD);
    float s = 0.f;
#pragma unroll
    for (int jj = 0; jj < 4; jj++) {
        float4 q = qp4[lane + 32 * jj];
        s += zv[jj].x*q.x + zv[jj].y*q.y + zv[jj].z*q.z + zv[jj].w*q.w;
    }
#pragma unroll
    for (int o = 16; o; o >>= 1) s += __shfl_xor_sync(0xFFFFFFFFu, s, o);
    return csq[c] - 2.f * s;
}

// ---------------------------------------------------------------------------
// init: residual = x (fp32 + bf16 hi), nl per row, reset loss/cmax. Warp/row.
// ---------------------------------------------------------------------------
__global__ void init_kernel(const float* __restrict__ x) {
    int row  = blockIdx.x * 8 + (threadIdx.x >> 5);
    int lane = threadIdx.x & 31;
    const float4* xp = (const float4*)(x + (size_t)row * DD);
    float4* rp = (float4*)(g_residual + (size_t)row * DD);
    ushort4* rh = (ushort4*)g_res_h4;
    float nls = 0.f;
#pragma unroll
    for (int j = 0; j < 4; j++) {
        float4 v = xp[lane + 32 * j];
        rp[lane + 32 * j] = v;
        ushort4 h = hi4(v);
        rh[(size_t)row * 128 + lane + 32 * j] = h;
        nls += losq4(v, h);
    }
#pragma unroll
    for (int o = 16; o; o >>= 1) nls += __shfl_xor_sync(0xFFFFFFFFu, nls, o);
    if (lane == 0) g_nl[row] = sqrtf(nls);
    if (blockIdx.x == 0 && threadIdx.x < BQ) {
        g_loss[threadIdx.x] = 0.f;
        g_cmaxi[threadIdx.x] = 0;
        g_nlcmaxi[threadIdx.x] = 0;
    }
}

// ---------------------------------------------------------------------------
// codebook: cb_sq + bf16 hi + per-codebook max csq and max lo-norm^2
// ---------------------------------------------------------------------------
__global__ void cbsq_kernel(const float* __restrict__ cb) {
    int row  = blockIdx.x * 8 + (threadIdx.x >> 5);   // 0 .. BQ*CC-1
    int lane = threadIdx.x & 31;
    const float4* p = (const float4*)(cb + (size_t)row * DD);
    ushort4* ch = (ushort4*)g_cb_h4;
    float s = 0.f, lsq = 0.f;
#pragma unroll
    for (int j = 0; j < 4; j++) {
        float4 v = p[lane + 32 * j];
        s += v.x * v.x + v.y * v.y + v.z * v.z + v.w * v.w;
        ushort4 h = hi4(v);
        ch[(size_t)row * 128 + lane + 32 * j] = h;
        lsq += losq4(v, h);
    }
#pragma unroll
    for (int o = 16; o; o >>= 1) {
        s += __shfl_xor_sync(0xFFFFFFFFu, s, o);
        lsq += __shfl_xor_sync(0xFFFFFFFFu, lsq, o);
    }
    if (lane == 0) {
        g_cbsq[row] = s;
        atomicMax(&g_cmaxi[row >> 10], __float_as_int(s));
        atomicMax(&g_nlcmaxi[row >> 10], __float_as_int(lsq));
    }
}

// ---------------------------------------------------------------------------
// hh-only distance GEMM (K=512 bf16) with per-thread top-3+v4 candidate lists.
// ---------------------------------------------------------------------------
#define PITCH   80
#define TILEB   (128 * PITCH)          // 10240 per operand
#define STAGEB  (2 * TILEB)            // 20480 A+B
#define NKC     16                     // hh segment only: 16 x 32 bf16 = 512
#define SMEM_DYN (4 * STAGEB)          // 81920

__device__ __forceinline__ void issue_chunk(
    uint32_t sb, int rowBase, int qi, int nt, int kc, int stage)
{
    int koff = kc * 64;
    uint32_t base = sb + stage * STAGEB;
    int tid = threadIdx.x;
    size_t bRow = (size_t)(qi * CC + nt * 128);
#pragma unroll
    for (int i = 0; i < 2; i++) {
        int g = tid + 256 * i;
        int r = g >> 2, c = g & 3;
        cpasync16(base + r * PITCH + c * 16,
                  (const char*)g_res_h4 + (size_t)(rowBase + r) * 1024 + koff + c * 16);
        cpasync16(base + TILEB + r * PITCH + c * 16,
                  (const char*)g_cb_h4 + (bRow + r) * 1024 + koff + c * 16);
    }
}

__global__ __launch_bounds__(256, 2) void dist_mma_kernel(int qi)
{
    extern __shared__ char smem[];
    uint32_t sb = smem_to_u32(smem);

    const int tid  = threadIdx.x;
    const int wid  = tid >> 5;
    const int lane = tid & 31;
    const int rowBase = blockIdx.x * 128;
    const int wM = (wid & 3) * 32;
    const int wN = (wid >> 2) * 64;

    const int aRow = lane & 15;
    const int aCol = (lane >> 4) * 16;
    const int bRowL = (lane & 7) + ((lane >> 4) << 3);
    const int bColL = ((lane >> 3) & 1) * 16;
    const uint32_t aOffBase = (uint32_t)((wM + aRow) * PITCH + aCol);
    const uint32_t bOffBase = (uint32_t)(TILEB + (wN + bRowL) * PITCH + bColL);

    const float2* csq2 = (const float2*)(g_cbsq + qi * CC);

    float cv1[4], cv2[4], cv3[4], cv4[4];
    int   ci1[4], ci2[4], ci3[4];
#pragma unroll
    for (int s = 0; s < 4; s++) {
        cv1[s] = INFINITY; cv2[s] = INFINITY; cv3[s] = INFINITY; cv4[s] = INFINITY;
        ci1[s] = 0x7fffffff; ci2[s] = 0x7fffffff; ci3[s] = 0x7fffffff;
    }

#pragma unroll 1
    for (int nt = 0; nt < 8; nt++) {
        float acc[2][8][4];
#pragma unroll
        for (int mf = 0; mf < 2; mf++)
#pragma unroll
            for (int nf = 0; nf < 8; nf++)
#pragma unroll
                for (int e = 0; e < 4; e++) acc[mf][nf][e] = 0.f;

        issue_chunk(sb, rowBase, qi, nt, 0, 0); CP_COMMIT();
        issue_chunk(sb, rowBase, qi, nt, 1, 1); CP_COMMIT();
        issue_chunk(sb, rowBase, qi, nt, 2, 2); CP_COMMIT();

#pragma unroll 1
        for (int kc = 0; kc < NKC; kc++) {
            if (kc < NKC - 2) { CP_WAIT(2); } else if (kc == NKC - 2) { CP_WAIT(1); }
            else { CP_WAIT(0); }
            __syncthreads();
            if (kc + 3 < NKC) {
                issue_chunk(sb, rowBase, qi, nt, kc + 3, (kc + 3) & 3);
                CP_COMMIT();
            }

            uint32_t stageBase = sb + (kc & 3) * STAGEB;
#pragma unroll
            for (int k16 = 0; k16 < 2; k16++) {
                uint32_t a[2][4];
#pragma unroll
                for (int mf = 0; mf < 2; mf++)
                    ldsm4(a[mf][0], a[mf][1], a[mf][2], a[mf][3],
                          stageBase + aOffBase + mf * 16 * PITCH + k16 * 32);
#pragma unroll
                for (int np = 0; np < 4; np++) {
                    uint32_t b0, b1, b2, b3;
                    ldsm4(b0, b1, b2, b3,
                          stageBase + bOffBase + np * 16 * PITCH + k16 * 32);
#pragma unroll
                    for (int mf = 0; mf < 2; mf++) {
                        mma16816(acc[mf][np * 2],
                                 a[mf][0], a[mf][1], a[mf][2], a[mf][3], b0, b1);
                        mma16816(acc[mf][np * 2 + 1],
                                 a[mf][0], a[mf][1], a[mf][2], a[mf][3], b2, b3);
                    }
                }
            }
        }
        __syncthreads();

#pragma unroll
        for (int mf = 0; mf < 2; mf++) {
#pragma unroll
            for (int nf = 0; nf < 8; nf++) {
                int n = nt * 128 + wN + nf * 8 + (lane & 3) * 2;
                float2 cq = csq2[n >> 1];
                float v0 = cq.x - 2.f * acc[mf][nf][0];
                float v1 = cq.y - 2.f * acc[mf][nf][1];
                float v2 = cq.x - 2.f * acc[mf][nf][2];
                float v3 = cq.y - 2.f * acc[mf][nf][3];
                int s0 = mf * 2, s1 = mf * 2 + 1;
                ins4(cv1[s0], ci1[s0], cv2[s0], ci2[s0], cv3[s0], ci3[s0], cv4[s0], v0, n);
                ins4(cv1[s0], ci1[s0], cv2[s0], ci2[s0], cv3[s0], ci3[s0], cv4[s0], v1, n + 1);
                ins4(cv1[s1], ci1[s1], cv2[s1], ci2[s1], cv3[s1], ci3[s1], cv4[s1], v2, n);
                ins4(cv1[s1], ci1[s1], cv2[s1], ci2[s1], cv3[s1], ci3[s1], cv4[s1], v3, n + 1);
            }
        }
    }

#pragma unroll
    for (int s = 0; s < 4; s++) {
        int row = rowBase + wM + (s >> 1) * 16 + (s & 1) * 8 + (lane >> 2);
        int contrib = (wid >> 2) * 4 + (lane & 3);
        size_t base = ((size_t)row * 8 + contrib) * 2;
        g_cand[base] = make_uint4(__float_as_uint(cv1[s]), (uint32_t)ci1[s],
                                  __float_as_uint(cv2[s]), (uint32_t)ci2[s]);
        g_cand[base + 1] = make_uint4(__float_as_uint(cv3[s]), (uint32_t)ci3[s],
                                      __float_as_uint(cv4[s]), 0u);
    }
}

// ---------------------------------------------------------------------------
// Exact argmin selection (narrow window; slot-local rescan fallback) +
// rotation trick + residual update + nl + loss + index. Warp per row.
// ---------------------------------------------------------------------------
__global__ void rotate_kernel(const float* __restrict__ cbs, int qi,
                              float* __restrict__ out_if,
                              int writeIdx, int writeLoss, int writeConv)
{
    __shared__ float ws[8];
    __shared__ int candList[8][24];
    int wslot = threadIdx.x >> 5;
    int row  = blockIdx.x * 8 + wslot;
    int lane = threadIdx.x & 31;
    float* zp = g_residual + (size_t)row * DD;

    float4 zv[4];
    float zz = 0.f;
#pragma unroll
    for (int j = 0; j < 4; j++) {
        zv[j] = ((const float4*)zp)[lane + 32 * j];
        zz += zv[j].x*zv[j].x + zv[j].y*zv[j].y + zv[j].z*zv[j].z + zv[j].w*zv[j].w;
    }
#pragma unroll
    for (int o = 16; o; o >>= 1) zz += __shfl_xor_sync(0xFFFFFFFFu, zz, o);
    float nz = sqrtf(zz);

    // ---- exact argmin selection ----
    float v1 = INFINITY, v2 = INFINITY, v3 = INFINITY, v4 = INFINITY;
    int i1 = 0x7fffffff, i2 = 0x7fffffff, i3 = 0x7fffffff;
    if (lane < 8) {
        uint4 a = g_cand[((size_t)row * 8 + lane) * 2];
        uint4 b = g_cand[((size_t)row * 8 + lane) * 2 + 1];
        v1 = __uint_as_float(a.x); i1 = (int)a.y;
        v2 = __uint_as_float(a.z); i2 = (int)a.w;
        v3 = __uint_as_float(b.x); i3 = (int)b.y;
        v4 = __uint_as_float(b.z);
    }
    float m = v1;
#pragma unroll
    for (int o = 16; o; o >>= 1) m = fminf(m, __shfl_xor_sync(0xFFFFFFFFu, m, o));

    // rigorous window from exact norms:
    // per-code error w = 2(nl*|c| + |rh|*|cl|) <= 2(nl*ncmax + (nz+nl)*nlcmax)
    // window width = 2w (triangle) + fp32-accum slack
    float nl = g_nl[row];
    float ncmax = sqrtf(__int_as_float(g_cmaxi[qi]));
    float nlcmax = sqrtf(__int_as_float(g_nlcmaxi[qi]));
    float win = m + 4.f * (nl * ncmax + (nz + nl) * nlcmax) + 0.2f;
    const float* csq = g_cbsq + qi * CC;

    unsigned oflMask = __ballot_sync(0xFFFFFFFFu, v4 <= win);   // lanes<8 only
    int myc = (v1 <= win ? 1 : 0) + (v2 <= win ? 1 : 0) + (v3 <= win ? 1 : 0);
    int tot = myc;
#pragma unroll
    for (int o = 16; o; o >>= 1) tot += __shfl_xor_sync(0xFFFFFFFFu, tot, o);

    int idx;
    if (oflMask == 0u && tot == 1) {
        unsigned bb = __ballot_sync(0xFFFFFFFFu, v1 == m);
        idx = __shfl_sync(0xFFFFFFFFu, i1, __ffs(bb) - 1);
    } else if (tot <= 24) {
        // gather listed in-window candidates
        int off = myc;
#pragma unroll
        for (int o = 1; o < 32; o <<= 1) {
            int t = __shfl_up_sync(0xFFFFFFFFu, off, o);
            if (lane >= o) off += t;
        }
        off -= myc;
        if (lane < 8) {
            int p = off;
            if (v1 <= win) candList[wslot][p++] = i1;
            if (v2 <= win) candList[wslot][p++] = i2;
            if (v3 <= win) candList[wslot][p++] = i3;
        }
        __syncwarp();
        float bd = INFINITY; int bi = 0x7fffffff;
        for (int j = 0; j < tot; j++) {
            int c = candList[wslot][j];
            float d = exact_d(cbs, csq, qi, c, zv, lane);
            if (d < bd || (d == bd && c < bi)) { bd = d; bi = c; }
        }
        // slot-local exact rescan for overflowed slots (4th+ may be in window)
        unsigned om = oflMask;
        while (om) {
            int sl = __ffs(om) - 1; om &= om - 1;     // contrib id 0..7
            int wNs = (sl >> 2) * 64;
            int l2  = (sl & 3) * 2;
            for (int j = 0; j < 128; j++) {
                int n = (j >> 4) * 128 + wNs + ((j >> 1) & 7) * 8 + l2 + (j & 1);
                float d = exact_d(cbs, csq, qi, n, zv, lane);
                if (d < bd || (d == bd && n < bi)) { bd = d; bi = n; }
            }
        }
        idx = bi;
    } else {
        // extreme fallback: exact full scan
        float bd = INFINITY; int bi = 0x7fffffff;
        for (int c = 0; c < CC; c++) {
            float d = exact_d(cbs, csq, qi, c, zv, lane);
            if (d < bd || (d == bd && c < bi)) { bd = d; bi = c; }
        }
        idx = bi;
    }

    // ---- rotation trick ----
    const float* qp = cbs + ((size_t)qi * CC + idx) * DD;
    float4 qv[4];
    float qq = 0.f, zq = 0.f, ll = 0.f;
#pragma unroll
    for (int j = 0; j < 4; j++) {
        qv[j] = ((const float4*)qp)[lane + 32 * j];
        qq += qv[j].x*qv[j].x + qv[j].y*qv[j].y + qv[j].z*qv[j].z + qv[j].w*qv[j].w;
        zq += zv[j].x*qv[j].x + zv[j].y*qv[j].y + zv[j].z*qv[j].z + zv[j].w*qv[j].w;
        float dx = qv[j].x - zv[j].x, dy = qv[j].y - zv[j].y;
        float dz = qv[j].z - zv[j].z, dw = qv[j].w - zv[j].w;
        ll += dx*dx + dy*dy + dz*dz + dw*dw;
    }
#pragma unroll
    for (int o = 16; o; o >>= 1) {
        qq += __shfl_xor_sync(0xFFFFFFFFu, qq, o);
        zq += __shfl_xor_sync(0xFFFFFFFFu, zq, o);
        ll += __shfl_xor_sync(0xFFFFFFFFu, ll, o);
    }

    float nq = sqrtf(qq);
    float iz = 1.f / (nz + EPSF), iq = 1.f / (nq + EPSF);
    float s2 = zz * iz * iz + 2.f * zq * iz * iq + qq * iq * iq;
    float A2 = 2.f * (zz * iz + zq * iq) / s2;
    float Bc = 2.f * zz * iz * iq;
    float cz = 1.f - A2 * iz;
    float cq = Bc - A2 * iq;
    float sc = nq * iz;

    ushort4* rh = (ushort4*)g_res_h4;
    float nls = 0.f;
#pragma unroll
    for (int j = 0; j < 4; j++) {
        float4 z = zv[j], q = qv[j], t, r;
        t.x = (z.x * cz + q.x * cq) * sc;
        t.y = (z.y * cz + q.y * cq) * sc;
        t.z = (z.z * cz + q.z * cq) * sc;
        t.w = (z.w * cz + q.w * cq) * sc;
        r.x = z.x - t.x; r.y = z.y - t.y; r.z = z.z - t.z; r.w = z.w - t.w;
        ((float4*)zp)[lane + 32 * j] = r;
        if (writeConv) {
            ushort4 h = hi4(r);
            rh[(size_t)row * 128 + lane + 32 * j] = h;
            nls += losq4(r, h);
        }
    }
    if (writeConv) {
#pragma unroll
        for (int o = 16; o; o >>= 1) nls += __shfl_xor_sync(0xFFFFFFFFu, nls, o);
        if (lane == 0) g_nl[row] = sqrtf(nls);
    }

    if (writeIdx && lane == 0)
        out_if[(size_t)row * BQ + qi] = (float)idx;

    if (writeLoss) {
        if (lane == 0) ws[wslot] = ll;
        __syncthreads();
        if (threadIdx.x == 0) {
            float s = 0.f;
#pragma unroll
            for (int w = 0; w < 8; w++) s += ws[w];
            atomicAdd(&g_loss[qi], s);
        }
    }
}

// ---------------------------------------------------------------------------
// out_q = x - residual_final  (sum of quants telescopes)
// ---------------------------------------------------------------------------
__global__ void outq_kernel(const float* __restrict__ x, float* __restrict__ out_q) {
    size_t i  = (size_t)blockIdx.x * blockDim.x + threadIdx.x;
    size_t n4 = (size_t)MROWS * DD / 4;
    const float4* x4 = (const float4*)x;
    const float4* r4 = (const float4*)g_residual;
    float4* o4 = (float4*)out_q;
    for (size_t k = i; k < n4; k += (size_t)gridDim.x * blockDim.x) {
        float4 a = x4[k], b = r4[k];
        o4[k] = make_float4(a.x - b.x, a.y - b.y, a.z - b.z, a.w - b.w);
    }
}

// ---------------------------------------------------------------------------
__global__ void final_kernel(float* __restrict__ out_loss) {
    int i = threadIdx.x;
    if (i < BQ) out_loss[i] = g_loss[i] / (float)((size_t)MROWS * DD);
}

// ---------------------------------------------------------------------------
extern "C" void kernel_launch(void* const* d_in, const int* in_sizes, int n_in,
                              void* d_out, int out_size) {
    const float* x   = (const float*)d_in[0];
    const float* cbs = (const float*)d_in[1];
    if (n_in >= 2 && in_sizes[0] == BQ * CC * DD && in_sizes[1] == MROWS * DD) {
        const float* t = x; x = cbs; cbs = t;
    }

    float* out = (float*)d_out;
    const long long qElems = (long long)MROWS * DD;   // 16777216
    const long long iElems = (long long)MROWS * BQ;   // 262144
    float* out_q = out;
    float* out_i = out + qElems;
    float* out_l = out + qElems + iElems;
    int haveIdx  = (out_size >= qElems + iElems) ? 1 : 0;
    int haveLoss = (out_size >= qElems + iElems + BQ) ? 1 : 0;

    static int attrSet = 0;
    if (!attrSet) {
        cudaFuncSetAttribute(dist_mma_kernel,
                             cudaFuncAttributeMaxDynamicSharedMemorySize, SMEM_DYN);
        attrSet = 1;
    }

    init_kernel<<<MROWS / 8, 256>>>(x);
    cbsq_kernel<<<BQ * CC / 8, 256>>>(cbs);

    for (int qi = 0; qi < BQ; qi++) {
        dist_mma_kernel<<<MROWS / 128, 256, SMEM_DYN>>>(qi);
        rotate_kernel<<<MROWS / 8, 256>>>(cbs, qi, out_i,
                                          haveIdx, haveLoss, qi < BQ - 1);
    }

    outq_kernel<<<1024, 256>>>(x, out_q);
    if (haveLoss) final_kernel<<<1, 32>>>(out_l);
}